// round 14
// baseline (speedup 1.0000x reference)
#include <cuda_runtime.h>
#include <math.h>

// Problem constants
#define NN     32
#define CC     512
#define HH     56
#define WW     56
#define HW     (HH * WW)          // 3136 floats per (n,c) row
#define FF     8                  // frequencies
#define OO     32                 // C / R
#define ROWS   (NN * CC)          // 16384
#define J_ROW  (HW / 4)           // 784 float4 per row

// sqrt(1/56) and sqrt(2/56)
#define B0S 0.1336306209562122f
#define BGS 0.1889822365046136f

// Scratch (no cudaMalloc allowed): intermediates live in device globals.
__device__ float g_y[NN * FF * CC];   // pooled DCT features (n, f, c)
__device__ float g_s[NN * CC];        // per-(n,c) sigmoid scale

__device__ __forceinline__ float dot4(float4 a, float4 b) {
    return fmaf(a.x, b.x, fmaf(a.y, b.y, fmaf(a.z, b.z, a.w * b.w)));
}

// ---------------------------------------------------------------------------
// Kernel 1: multi-frequency DCT pooling, SEPARABLE form.
//   filt[f,h,w] = bH_{u_f}[h] * bW_{v_f}[w]; only 4 distinct 56-pt bases
//   built analytically in 1.8 KB smem (no dct traffic, no hot-loop barriers).
// v5: unroll j by 2 with all 4 LDG.128 batched up front (MLP=4/warp), clean
// 12-iteration hot loop + separate tail (no clamping/branching inside).
//   f -> (gH, gW): [ (0,0) (0,1) (1,0) (1,1) (0,3) (3,0) (0,2) (2,0) ]
// Grid: 2048 blocks x 128 thr (4 warps x 2 rows = 8 rows/block).
// ---------------------------------------------------------------------------
__global__ __launch_bounds__(128, 6)
void freq_pool_kernel(const float* __restrict__ x)
{
    __shared__ float4 sBH[56];      // sBH[h] = {b0,b1,b2,b3}(h)
    __shared__ float4 sBW[4][14];   // sBW[g][wq] = b_g(4wq .. 4wq+3)

    const int tid = threadIdx.x;
    if (tid < 56) {
        const float p = (tid + 0.5f) / 56.0f;
        sBH[tid] = make_float4(B0S,
                               cospif(1.0f * p) * BGS,
                               cospif(2.0f * p) * BGS,
                               cospif(3.0f * p) * BGS);
    } else if (tid >= 64 && tid < 120) {
        const int idx = tid - 64;
        const int g = idx / 14, wq = idx - g * 14;
        const float s = g ? BGS : B0S;
        const float fg = (float)g;
        float4 v;
        v.x = cospif(fg * (4 * wq + 0.5f) / 56.0f) * s;
        v.y = cospif(fg * (4 * wq + 1.5f) / 56.0f) * s;
        v.z = cospif(fg * (4 * wq + 2.5f) / 56.0f) * s;
        v.w = cospif(fg * (4 * wq + 3.5f) / 56.0f) * s;
        sBW[g][wq] = v;
    }
    __syncthreads();

    const int warp = tid >> 5;
    const int lane = tid & 31;
    const int row0 = (blockIdx.x * 4 + warp) * 2;   // pair of rows

    const float4* xb = (const float4*)x + (size_t)row0 * J_ROW;

    float acc0[FF], acc1[FF];
#pragma unroll
    for (int f = 0; f < FF; f++) { acc0[f] = 0.0f; acc1[f] = 0.0f; }

    // 784 float4/row, stride 32: j = lane + 32k, k = 0..23 full (tail below).
#pragma unroll 1
    for (int k = 0; k < 24; k += 2) {
        const int j  = lane + 32 * k;
        const int j2 = j + 32;
        // 4 independent global loads batched up front (MLP = 4)
        const float4 c0 = xb[j];
        const float4 c1 = xb[j  + J_ROW];
        const float4 d0 = xb[j2];
        const float4 d1 = xb[j2 + J_ROW];

        // position j
        {
            const int h  = j / 14;
            const int wq = j - h * 14;
            const float4 bh = sBH[h];
            const float4 w0 = sBW[0][wq];
            const float4 w1 = sBW[1][wq];
            const float4 w2 = sBW[2][wq];
            const float4 w3 = sBW[3][wq];
            const float e0 = dot4(c0, w0), e1 = dot4(c0, w1);
            const float e2 = dot4(c0, w2), e3 = dot4(c0, w3);
            acc0[0] = fmaf(bh.x, e0, acc0[0]);
            acc0[1] = fmaf(bh.x, e1, acc0[1]);
            acc0[2] = fmaf(bh.y, e0, acc0[2]);
            acc0[3] = fmaf(bh.y, e1, acc0[3]);
            acc0[4] = fmaf(bh.x, e3, acc0[4]);
            acc0[5] = fmaf(bh.w, e0, acc0[5]);
            acc0[6] = fmaf(bh.x, e2, acc0[6]);
            acc0[7] = fmaf(bh.z, e0, acc0[7]);
            const float g0 = dot4(c1, w0), g1 = dot4(c1, w1);
            const float g2 = dot4(c1, w2), g3 = dot4(c1, w3);
            acc1[0] = fmaf(bh.x, g0, acc1[0]);
            acc1[1] = fmaf(bh.x, g1, acc1[1]);
            acc1[2] = fmaf(bh.y, g0, acc1[2]);
            acc1[3] = fmaf(bh.y, g1, acc1[3]);
            acc1[4] = fmaf(bh.x, g3, acc1[4]);
            acc1[5] = fmaf(bh.w, g0, acc1[5]);
            acc1[6] = fmaf(bh.x, g2, acc1[6]);
            acc1[7] = fmaf(bh.z, g0, acc1[7]);
        }
        // position j2
        {
            const int h  = j2 / 14;
            const int wq = j2 - h * 14;
            const float4 bh = sBH[h];
            const float4 w0 = sBW[0][wq];
            const float4 w1 = sBW[1][wq];
            const float4 w2 = sBW[2][wq];
            const float4 w3 = sBW[3][wq];
            const float e0 = dot4(d0, w0), e1 = dot4(d0, w1);
            const float e2 = dot4(d0, w2), e3 = dot4(d0, w3);
            acc0[0] = fmaf(bh.x, e0, acc0[0]);
            acc0[1] = fmaf(bh.x, e1, acc0[1]);
            acc0[2] = fmaf(bh.y, e0, acc0[2]);
            acc0[3] = fmaf(bh.y, e1, acc0[3]);
            acc0[4] = fmaf(bh.x, e3, acc0[4]);
            acc0[5] = fmaf(bh.w, e0, acc0[5]);
            acc0[6] = fmaf(bh.x, e2, acc0[6]);
            acc0[7] = fmaf(bh.z, e0, acc0[7]);
            const float g0 = dot4(d1, w0), g1 = dot4(d1, w1);
            const float g2 = dot4(d1, w2), g3 = dot4(d1, w3);
            acc1[0] = fmaf(bh.x, g0, acc1[0]);
            acc1[1] = fmaf(bh.x, g1, acc1[1]);
            acc1[2] = fmaf(bh.y, g0, acc1[2]);
            acc1[3] = fmaf(bh.y, g1, acc1[3]);
            acc1[4] = fmaf(bh.x, g3, acc1[4]);
            acc1[5] = fmaf(bh.w, g0, acc1[5]);
            acc1[6] = fmaf(bh.x, g2, acc1[6]);
            acc1[7] = fmaf(bh.z, g0, acc1[7]);
        }
    }
    // tail: j = 768 + lane, valid for lane < 16 (768..783)
    if (lane < 16) {
        const int j = 768 + lane;
        const float4 c0 = xb[j];
        const float4 c1 = xb[j + J_ROW];
        const int h  = j / 14;
        const int wq = j - h * 14;
        const float4 bh = sBH[h];
        const float4 w0 = sBW[0][wq];
        const float4 w1 = sBW[1][wq];
        const float4 w2 = sBW[2][wq];
        const float4 w3 = sBW[3][wq];
        const float e0 = dot4(c0, w0), e1 = dot4(c0, w1);
        const float e2 = dot4(c0, w2), e3 = dot4(c0, w3);
        acc0[0] = fmaf(bh.x, e0, acc0[0]);
        acc0[1] = fmaf(bh.x, e1, acc0[1]);
        acc0[2] = fmaf(bh.y, e0, acc0[2]);
        acc0[3] = fmaf(bh.y, e1, acc0[3]);
        acc0[4] = fmaf(bh.x, e3, acc0[4]);
        acc0[5] = fmaf(bh.w, e0, acc0[5]);
        acc0[6] = fmaf(bh.x, e2, acc0[6]);
        acc0[7] = fmaf(bh.z, e0, acc0[7]);
        const float g0 = dot4(c1, w0), g1 = dot4(c1, w1);
        const float g2 = dot4(c1, w2), g3 = dot4(c1, w3);
        acc1[0] = fmaf(bh.x, g0, acc1[0]);
        acc1[1] = fmaf(bh.x, g1, acc1[1]);
        acc1[2] = fmaf(bh.y, g0, acc1[2]);
        acc1[3] = fmaf(bh.y, g1, acc1[3]);
        acc1[4] = fmaf(bh.x, g3, acc1[4]);
        acc1[5] = fmaf(bh.w, g0, acc1[5]);
        acc1[6] = fmaf(bh.x, g2, acc1[6]);
        acc1[7] = fmaf(bh.z, g0, acc1[7]);
    }

    // Warp reduce the 16 sums; lane 0 stores.
#pragma unroll
    for (int r = 0; r < 2; r++) {
        const int row = row0 + r;
        const int n = row >> 9;             // /CC
        const int c = row & (CC - 1);
#pragma unroll
        for (int f = 0; f < FF; f++) {
            float v = r ? acc1[f] : acc0[f];
#pragma unroll
            for (int off = 16; off > 0; off >>= 1)
                v += __shfl_xor_sync(0xffffffffu, v, off);
            if (lane == 0)
                g_y[(size_t)n * FF * CC + f * CC + c] = v;
        }
    }
}

// ---------------------------------------------------------------------------
// Kernel 2: squeeze-excite MLP (tiny). One block per sample n.
//   z[f,o] = relu( sum_c y[n,f,c] * w1[f,o,c] )        (w1: (8,32,512))
//   s[c]   = sigmoid( sum_{f,o} z[f,o] * w2[c,f,o] )   (w2: (512,8,32))
// ---------------------------------------------------------------------------
__global__ __launch_bounds__(256, 4)
void freq_mlp_kernel(const float* __restrict__ w1,
                     const float* __restrict__ w2)
{
    __shared__ __align__(16) float zs[FF * OO];   // 256 floats

    const int n = blockIdx.x;
    const int t = threadIdx.x;

    // Phase A: 256 threads -> one (f,o) each, dot over C=512.
    {
        const int f = t >> 5;
        const int o = t & 31;
        const float4* yv = (const float4*)(g_y + (size_t)n * FF * CC + f * CC);
        const float4* wv = (const float4*)(w1 + (size_t)(f * OO + o) * CC);
        float s = 0.0f;
#pragma unroll 8
        for (int i = 0; i < CC / 4; i++) {
            float4 a = yv[i];
            float4 b = wv[i];
            s = fmaf(a.x, b.x, fmaf(a.y, b.y, fmaf(a.z, b.z, fmaf(a.w, b.w, s))));
        }
        zs[f * OO + o] = fmaxf(s, 0.0f);
    }
    __syncthreads();

    // Phase B: each thread handles 2 output channels, dot over F*O=256.
    for (int c = t; c < CC; c += 256) {
        const float4* wv = (const float4*)(w2 + (size_t)c * FF * OO);
        const float4* zv = (const float4*)zs;
        float s = 0.0f;
#pragma unroll 8
        for (int i = 0; i < (FF * OO) / 4; i++) {
            float4 a = zv[i];
            float4 b = wv[i];
            s = fmaf(a.x, b.x, fmaf(a.y, b.y, fmaf(a.z, b.z, fmaf(a.w, b.w, s))));
        }
        g_s[n * CC + c] = 1.0f / (1.0f + __expf(-s));
    }
}

// ---------------------------------------------------------------------------
// Kernel 3: broadcast channel scale (pure stream).
// v4: 4 independent float4 per thread (1024-float4 tile per block, stride
// 256) -> 4 LDG.128 + 4 STG.128 in flight; streaming cache hints.
// Grid: 12544 blocks x 256 thr (12544*1024 = 12,845,056 float4 exactly).
// ---------------------------------------------------------------------------
__global__ __launch_bounds__(256, 8)
void freq_scale_kernel(const float* __restrict__ x,
                       float* __restrict__ out)
{
    const int base = blockIdx.x * 1024 + threadIdx.x;
    const int i0 = base;
    const int i1 = base + 256;
    const int i2 = base + 512;
    const int i3 = base + 768;

    float4 v0 = __ldcs((const float4*)x + i0);
    float4 v1 = __ldcs((const float4*)x + i1);
    float4 v2 = __ldcs((const float4*)x + i2);
    float4 v3 = __ldcs((const float4*)x + i3);

    const float s0 = __ldg(&g_s[i0 / J_ROW]);
    const float s1 = __ldg(&g_s[i1 / J_ROW]);
    const float s2 = __ldg(&g_s[i2 / J_ROW]);
    const float s3 = __ldg(&g_s[i3 / J_ROW]);

    v0.x *= s0; v0.y *= s0; v0.z *= s0; v0.w *= s0;
    v1.x *= s1; v1.y *= s1; v1.z *= s1; v1.w *= s1;
    v2.x *= s2; v2.y *= s2; v2.z *= s2; v2.w *= s2;
    v3.x *= s3; v3.y *= s3; v3.z *= s3; v3.w *= s3;

    __stcs((float4*)out + i0, v0);
    __stcs((float4*)out + i1, v1);
    __stcs((float4*)out + i2, v2);
    __stcs((float4*)out + i3, v3);
}

// ---------------------------------------------------------------------------
// Launch. Inputs (metadata order): x, dct, w1, w2. Output: fp32 (N,C,H,W).
// (dct input no longer needed: basis is rebuilt analytically in-kernel.)
// ---------------------------------------------------------------------------
extern "C" void kernel_launch(void* const* d_in, const int* in_sizes, int n_in,
                              void* d_out, int out_size)
{
    const float* x   = (const float*)d_in[0];
    const float* w1  = (const float*)d_in[2];
    const float* w2  = (const float*)d_in[3];
    float* out = (float*)d_out;

    freq_pool_kernel<<<2048, 128>>>(x);

    freq_mlp_kernel<<<NN, 256>>>(w1, w2);

    freq_scale_kernel<<<(ROWS * J_ROW) / 1024, 256>>>(x, out);
}

// round 15
// speedup vs baseline: 1.0345x; 1.0345x over previous
#include <cuda_runtime.h>
#include <math.h>

// Problem constants
#define NN     32
#define CC     512
#define HH     56
#define WW     56
#define HW     (HH * WW)          // 3136 floats per (n,c) row
#define FF     8                  // frequencies
#define OO     32                 // C / R
#define ROWS   (NN * CC)          // 16384
#define J_ROW  (HW / 4)           // 784 float4 per row

// sqrt(1/56) and sqrt(2/56)
#define B0S 0.1336306209562122f
#define BGS 0.1889822365046136f

// Scratch (no cudaMalloc allowed): intermediates live in device globals.
__device__ float g_y[NN * FF * CC];   // pooled DCT features (n, f, c)
__device__ float g_s[NN * CC];        // per-(n,c) sigmoid scale

__device__ __forceinline__ float dot4(float4 a, float4 b) {
    return fmaf(a.x, b.x, fmaf(a.y, b.y, fmaf(a.z, b.z, a.w * b.w)));
}

// f -> (gH, gW): [ (0,0) (0,1) (1,0) (1,1) (0,3) (3,0) (0,2) (2,0) ]
__device__ __forceinline__ void accum(float acc[FF], float4 c, float4 bh,
                                      float4 w0, float4 w1,
                                      float4 w2, float4 w3)
{
    const float d0 = dot4(c, w0), d1 = dot4(c, w1);
    const float d2 = dot4(c, w2), d3 = dot4(c, w3);
    acc[0] = fmaf(bh.x, d0, acc[0]);
    acc[1] = fmaf(bh.x, d1, acc[1]);
    acc[2] = fmaf(bh.y, d0, acc[2]);
    acc[3] = fmaf(bh.y, d1, acc[3]);
    acc[4] = fmaf(bh.x, d3, acc[4]);
    acc[5] = fmaf(bh.w, d0, acc[5]);
    acc[6] = fmaf(bh.x, d2, acc[6]);
    acc[7] = fmaf(bh.z, d0, acc[7]);
}

// ---------------------------------------------------------------------------
// Kernel 1: multi-frequency DCT pooling, SEPARABLE form, fixed-wq lanes.
//   filt[f,h,w] = bH_{u_f}[h] * bW_{v_f}[w]; 4 distinct 56-pt bases.
// v6: lane l<28 owns fixed W-column block wq=l%14, image-row parity dh=l/14.
//   -> the 4 bW float4s are LOOP-INVARIANT REGISTERS (no bW LDS in hot loop;
//   only one broadcast sBH[h] per position). Lanes 28-31 idle (bW zeroed).
// Per warp: 2 channel rows; per iteration 4 image rows = 4 batched LDG.128,
//   2 LDS, 96 FMA. 14 iterations covers all 56 image rows.
// Grid: 2048 blocks x 128 thr (4 warps x 2 rows = 8 rows/block).
// ---------------------------------------------------------------------------
__global__ __launch_bounds__(128, 7)
void freq_pool_kernel(const float* __restrict__ x)
{
    __shared__ float4 sBH[56];      // sBH[h] = {b0,b1,b2,b3}(h)
    __shared__ float4 sBW[4][14];   // sBW[g][wq] = b_g(4wq .. 4wq+3)

    const int tid = threadIdx.x;
    if (tid < 56) {
        const float p = (tid + 0.5f) / 56.0f;
        sBH[tid] = make_float4(B0S,
                               cospif(1.0f * p) * BGS,
                               cospif(2.0f * p) * BGS,
                               cospif(3.0f * p) * BGS);
    } else if (tid >= 64 && tid < 120) {
        const int idx = tid - 64;
        const int g = idx / 14, wq = idx - g * 14;
        const float s = g ? BGS : B0S;
        const float fg = (float)g;
        float4 v;
        v.x = cospif(fg * (4 * wq + 0.5f) / 56.0f) * s;
        v.y = cospif(fg * (4 * wq + 1.5f) / 56.0f) * s;
        v.z = cospif(fg * (4 * wq + 2.5f) / 56.0f) * s;
        v.w = cospif(fg * (4 * wq + 3.5f) / 56.0f) * s;
        sBW[g][wq] = v;
    }
    __syncthreads();

    const int warp = tid >> 5;
    const int lane = tid & 31;
    const int row0 = (blockIdx.x * 4 + warp) * 2;   // pair of channel rows

    // Fixed lane mapping: wq = lane % 14, dh = lane / 14; lanes >= 28 idle.
    const bool active = lane < 28;
    const int  wq = active ? (lane % 14) : 0;
    const int  dh = active ? (lane / 14) : 0;

    // Loop-invariant W-basis registers (zeroed for idle lanes -> acc stays 0).
    float4 bw0 = sBW[0][wq];
    float4 bw1 = sBW[1][wq];
    float4 bw2 = sBW[2][wq];
    float4 bw3 = sBW[3][wq];
    if (!active) {
        bw0 = make_float4(0.f, 0.f, 0.f, 0.f);
        bw1 = bw0; bw2 = bw0; bw3 = bw0;
    }

    const float4* xb = (const float4*)x + (size_t)row0 * J_ROW;

    float acc0[FF], acc1[FF];
#pragma unroll
    for (int f = 0; f < FF; f++) { acc0[f] = 0.0f; acc1[f] = 0.0f; }

    // 14 iterations x 4 image rows (hA=4it+dh covers parities via dh).
#pragma unroll 2
    for (int it = 0; it < 14; it++) {
        const int hA = 4 * it + dh;
        const int hB = hA + 2;
        const int pA = hA * 14 + wq;        // float4 index within channel row
        const int pB = hB * 14 + wq;

        // 4 independent global loads batched up front (MLP = 4)
        const float4 cA0 = xb[pA];
        const float4 cA1 = xb[pA + J_ROW];
        const float4 cB0 = xb[pB];
        const float4 cB1 = xb[pB + J_ROW];

        const float4 bhA = sBH[hA];
        const float4 bhB = sBH[hB];

        accum(acc0, cA0, bhA, bw0, bw1, bw2, bw3);
        accum(acc1, cA1, bhA, bw0, bw1, bw2, bw3);
        accum(acc0, cB0, bhB, bw0, bw1, bw2, bw3);
        accum(acc1, cB1, bhB, bw0, bw1, bw2, bw3);
    }

    // Warp reduce the 16 sums (idle lanes contribute 0); lane 0 stores.
#pragma unroll
    for (int r = 0; r < 2; r++) {
        const int row = row0 + r;
        const int n = row >> 9;             // /CC
        const int c = row & (CC - 1);
#pragma unroll
        for (int f = 0; f < FF; f++) {
            float v = r ? acc1[f] : acc0[f];
#pragma unroll
            for (int off = 16; off > 0; off >>= 1)
                v += __shfl_xor_sync(0xffffffffu, v, off);
            if (lane == 0)
                g_y[(size_t)n * FF * CC + f * CC + c] = v;
        }
    }
}

// ---------------------------------------------------------------------------
// Kernel 2: squeeze-excite MLP (tiny). One block per sample n.
//   z[f,o] = relu( sum_c y[n,f,c] * w1[f,o,c] )        (w1: (8,32,512))
//   s[c]   = sigmoid( sum_{f,o} z[f,o] * w2[c,f,o] )   (w2: (512,8,32))
// ---------------------------------------------------------------------------
__global__ __launch_bounds__(256, 4)
void freq_mlp_kernel(const float* __restrict__ w1,
                     const float* __restrict__ w2)
{
    __shared__ __align__(16) float zs[FF * OO];   // 256 floats

    const int n = blockIdx.x;
    const int t = threadIdx.x;

    // Phase A: 256 threads -> one (f,o) each, dot over C=512.
    {
        const int f = t >> 5;
        const int o = t & 31;
        const float4* yv = (const float4*)(g_y + (size_t)n * FF * CC + f * CC);
        const float4* wv = (const float4*)(w1 + (size_t)(f * OO + o) * CC);
        float s = 0.0f;
#pragma unroll 8
        for (int i = 0; i < CC / 4; i++) {
            float4 a = yv[i];
            float4 b = wv[i];
            s = fmaf(a.x, b.x, fmaf(a.y, b.y, fmaf(a.z, b.z, fmaf(a.w, b.w, s))));
        }
        zs[f * OO + o] = fmaxf(s, 0.0f);
    }
    __syncthreads();

    // Phase B: each thread handles 2 output channels, dot over F*O=256.
    for (int c = t; c < CC; c += 256) {
        const float4* wv = (const float4*)(w2 + (size_t)c * FF * OO);
        const float4* zv = (const float4*)zs;
        float s = 0.0f;
#pragma unroll 8
        for (int i = 0; i < (FF * OO) / 4; i++) {
            float4 a = zv[i];
            float4 b = wv[i];
            s = fmaf(a.x, b.x, fmaf(a.y, b.y, fmaf(a.z, b.z, fmaf(a.w, b.w, s))));
        }
        g_s[n * CC + c] = 1.0f / (1.0f + __expf(-s));
    }
}

// ---------------------------------------------------------------------------
// Kernel 3: broadcast channel scale (pure stream, at R+W ceiling ~4.3 TB/s).
// 4 independent float4 per thread, streaming cache hints.
// Grid: 12544 blocks x 256 thr (12544*1024 = 12,845,056 float4 exactly).
// ---------------------------------------------------------------------------
__global__ __launch_bounds__(256, 8)
void freq_scale_kernel(const float* __restrict__ x,
                       float* __restrict__ out)
{
    const int base = blockIdx.x * 1024 + threadIdx.x;
    const int i0 = base;
    const int i1 = base + 256;
    const int i2 = base + 512;
    const int i3 = base + 768;

    float4 v0 = __ldcs((const float4*)x + i0);
    float4 v1 = __ldcs((const float4*)x + i1);
    float4 v2 = __ldcs((const float4*)x + i2);
    float4 v3 = __ldcs((const float4*)x + i3);

    const float s0 = __ldg(&g_s[i0 / J_ROW]);
    const float s1 = __ldg(&g_s[i1 / J_ROW]);
    const float s2 = __ldg(&g_s[i2 / J_ROW]);
    const float s3 = __ldg(&g_s[i3 / J_ROW]);

    v0.x *= s0; v0.y *= s0; v0.z *= s0; v0.w *= s0;
    v1.x *= s1; v1.y *= s1; v1.z *= s1; v1.w *= s1;
    v2.x *= s2; v2.y *= s2; v2.z *= s2; v2.w *= s2;
    v3.x *= s3; v3.y *= s3; v3.z *= s3; v3.w *= s3;

    __stcs((float4*)out + i0, v0);
    __stcs((float4*)out + i1, v1);
    __stcs((float4*)out + i2, v2);
    __stcs((float4*)out + i3, v3);
}

// ---------------------------------------------------------------------------
// Launch. Inputs (metadata order): x, dct, w1, w2. Output: fp32 (N,C,H,W).
// (dct input no longer needed: basis is rebuilt analytically in-kernel.)
// ---------------------------------------------------------------------------
extern "C" void kernel_launch(void* const* d_in, const int* in_sizes, int n_in,
                              void* d_out, int out_size)
{
    const float* x   = (const float*)d_in[0];
    const float* w1  = (const float*)d_in[2];
    const float* w2  = (const float*)d_in[3];
    float* out = (float*)d_out;

    freq_pool_kernel<<<2048, 128>>>(x);

    freq_mlp_kernel<<<NN, 256>>>(w1, w2);

    freq_scale_kernel<<<(ROWS * J_ROW) / 1024, 256>>>(x, out);
}